// round 6
// baseline (speedup 1.0000x reference)
#include <cuda_runtime.h>
#include <cuda_bf16.h>
#include <math.h>

// Problem constants (match reference)
#define MAXN 10000
#define MAXE 40000
#define MAXG 128
#define NF 92
#define EF 50
#define HD 64
#define NHEAD 10
#define GD 108
#define NL 5
#define HW (NHEAD*HD)   // 640

// ---------------- static device scratch (no allocations allowed) -------------
__device__ float g_h[MAXN*HD];       // current node features
__device__ float g_h0[MAXN*HD];      // initial embedding (residual)
__device__ float g_ea[MAXE*HD];      // edge embedding
__device__ float g_P[MAXN*HW];       // h @ W_top      (per layer)
__device__ float g_Q[(size_t)MAXE*HW]; // ea @ W_bot   (per layer)
__device__ float g_hagg[MAXN*HD];    // aggregated messages
__device__ float g_GB[MAXG*HD];      // global_features @ ga_W1[64:] + b1
__device__ float g_score[MAXN];
__device__ float g_ex[MAXN];
__device__ unsigned g_smax[MAXG];    // ordered-float max keys
__device__ float g_denom[MAXG];
__device__ float g_pooled[MAXG*HD];

__device__ __forceinline__ float lrelu(float v) { return v > 0.f ? v : 0.2f * v; }

__device__ __forceinline__ unsigned f2o(float f) {
    unsigned u = __float_as_uint(f);
    return (u & 0x80000000u) ? ~u : (u | 0x80000000u);
}
__device__ __forceinline__ float o2f(unsigned u) {
    return (u & 0x80000000u) ? __uint_as_float(u ^ 0x80000000u) : __uint_as_float(~u);
}

// f32x2 packed helpers (Blackwell sm_100+)
__device__ __forceinline__ unsigned long long f32x2_dup(float s) {
    unsigned u = __float_as_uint(s);
    unsigned long long d;
    asm("mov.b64 %0, {%1, %1};" : "=l"(d) : "r"(u));
    return d;
}
__device__ __forceinline__ void f32x2_fma(unsigned long long& acc,
                                          unsigned long long a,
                                          unsigned long long b) {
    asm("fma.rn.f32x2 %0, %1, %2, %0;" : "+l"(acc) : "l"(a), "l"(b));
}
__device__ __forceinline__ void f32x2_unpack(float& lo, float& hi, unsigned long long v) {
    unsigned a, b;
    asm("mov.b64 {%0, %1}, %2;" : "=r"(a), "=r"(b) : "l"(v));
    lo = __uint_as_float(a); hi = __uint_as_float(b);
}

// ---------------- fused P/Q GEMM, K=64, Nc multiple of 128 -------------------
// C[M,640] = A[M,64] @ W[64,640].  128x128 tile, 256 threads, 8x8 microtile,
// f32x2 packed accumulation (pairs along N).
__global__ __launch_bounds__(256, 2)
void gemm_pq(const float* __restrict__ A1, const float* __restrict__ A2,
             const float* __restrict__ W1, const float* __restrict__ W2,
             float* __restrict__ C1, float* __restrict__ C2,
             int M1, int M2, int nb1)
{
    __shared__ float As[32][128];
    __shared__ float Ws[32][128];

    const float* A; const float* W; float* C; int M; int row0;
    if ((int)blockIdx.x < nb1) {
        A = A1; W = W1; C = C1; M = M1; row0 = blockIdx.x * 128;
    } else {
        A = A2; W = W2; C = C2; M = M2; row0 = (blockIdx.x - nb1) * 128;
    }
    const int col0 = blockIdx.y * 128;
    const int tid = threadIdx.x;
    const int tx = tid & 15;       // col group (8 cols)
    const int ty = tid >> 4;       // row group (8 rows)

    unsigned long long acc[8][4];
#pragma unroll
    for (int i = 0; i < 8; i++)
#pragma unroll
        for (int j = 0; j < 4; j++) acc[i][j] = 0ULL;

#pragma unroll
    for (int k0 = 0; k0 < 64; k0 += 32) {
        // Load A chunk: 128 rows x 32 k (transpose into As[k][row])
#pragma unroll
        for (int i = 0; i < 4; i++) {
            int idx = tid + 256 * i;       // 0..1023
            int r = idx & 127;
            int kg = idx >> 7;             // 0..7 -> 4 k's each
            int gr = row0 + r;
            float4 v;
            if (gr < M) v = *(const float4*)&A[(size_t)gr * 64 + k0 + kg * 4];
            else        v = make_float4(0.f, 0.f, 0.f, 0.f);
            As[kg * 4 + 0][r] = v.x;
            As[kg * 4 + 1][r] = v.y;
            As[kg * 4 + 2][r] = v.z;
            As[kg * 4 + 3][r] = v.w;
        }
        // Load W chunk: 32 k x 128 cols (direct copy)
#pragma unroll
        for (int i = 0; i < 4; i++) {
            int idx = tid + 256 * i;       // 0..1023
            int kk = idx >> 5;             // 0..31
            int c4 = (idx & 31) * 4;       // 0..124
            *(float4*)&Ws[kk][c4] = *(const float4*)&W[(size_t)(k0 + kk) * HW + col0 + c4];
        }
        __syncthreads();

#pragma unroll
        for (int kk = 0; kk < 32; kk++) {
            float4 a0 = *(const float4*)&As[kk][ty * 8];
            float4 a1 = *(const float4*)&As[kk][ty * 8 + 4];
            ulonglong2 bA = *(const ulonglong2*)&Ws[kk][tx * 8];
            ulonglong2 bB = *(const ulonglong2*)&Ws[kk][tx * 8 + 4];
            unsigned long long b[4] = {bA.x, bA.y, bB.x, bB.y};
            unsigned long long ad[8];
            ad[0] = f32x2_dup(a0.x); ad[1] = f32x2_dup(a0.y);
            ad[2] = f32x2_dup(a0.z); ad[3] = f32x2_dup(a0.w);
            ad[4] = f32x2_dup(a1.x); ad[5] = f32x2_dup(a1.y);
            ad[6] = f32x2_dup(a1.z); ad[7] = f32x2_dup(a1.w);
#pragma unroll
            for (int i = 0; i < 8; i++)
#pragma unroll
                for (int j = 0; j < 4; j++)
                    f32x2_fma(acc[i][j], ad[i], b[j]);
        }
        __syncthreads();
    }

    // Epilogue: unpack and store
#pragma unroll
    for (int i = 0; i < 8; i++) {
        int r = row0 + ty * 8 + i;
        if (r >= M) continue;
        float c[8];
#pragma unroll
        for (int j = 0; j < 4; j++) f32x2_unpack(c[2 * j], c[2 * j + 1], acc[i][j]);
        float4 f0 = make_float4(c[0], c[1], c[2], c[3]);
        float4 f1 = make_float4(c[4], c[5], c[6], c[7]);
        float* dst = C + (size_t)r * HW + col0 + tx * 8;
        *(float4*)dst       = f0;
        *(float4*)(dst + 4) = f1;
    }
}

// ---------------- tiled fp32 GEMM (embeddings): small, generic ---------------
__global__ void gemm_tiled(const float* __restrict__ A, int lda,
                           const float* __restrict__ W, int ldw,
                           const float* __restrict__ bias,
                           float* __restrict__ C, int ldc,
                           int M, int K, int act)
{
    __shared__ float As[16][64];
    __shared__ float Ws[16][64];
    const int row0 = blockIdx.x * 64;
    const int col0 = blockIdx.y * 64;
    const int tid = threadIdx.x;
    const int tx = tid & 15, ty = tid >> 4;

    float acc[4][4];
#pragma unroll
    for (int i = 0; i < 4; i++)
#pragma unroll
        for (int j = 0; j < 4; j++) acc[i][j] = 0.f;

    for (int k0 = 0; k0 < K; k0 += 16) {
#pragma unroll
        for (int i = 0; i < 4; i++) {
            int e = tid + 256 * i;
            int r = e >> 4, kk = e & 15;
            int gr = row0 + r, gk = k0 + kk;
            As[kk][r] = (gr < M && gk < K) ? A[(size_t)gr * lda + gk] : 0.f;
        }
#pragma unroll
        for (int i = 0; i < 4; i++) {
            int e = tid + 256 * i;
            int kk = e >> 6, c = e & 63;
            int gk = k0 + kk;
            Ws[kk][c] = (gk < K) ? W[(size_t)gk * ldw + col0 + c] : 0.f;
        }
        __syncthreads();
#pragma unroll
        for (int kk = 0; kk < 16; kk++) {
            float4 a = *(const float4*)&As[kk][ty * 4];
            float4 b = *(const float4*)&Ws[kk][tx * 4];
            float av[4] = {a.x, a.y, a.z, a.w};
            float bv[4] = {b.x, b.y, b.z, b.w};
#pragma unroll
            for (int i = 0; i < 4; i++)
#pragma unroll
                for (int j = 0; j < 4; j++) acc[i][j] += av[i] * bv[j];
        }
        __syncthreads();
    }
#pragma unroll
    for (int i = 0; i < 4; i++) {
        int r = row0 + ty * 4 + i;
        if (r >= M) continue;
#pragma unroll
        for (int j = 0; j < 4; j++) {
            int c = col0 + tx * 4 + j;
            float v = acc[i][j];
            if (bias) v += bias[c];
            if (act) v = lrelu(v);
            C[(size_t)r * ldc + c] = v;
        }
    }
}

// ---------------- per-edge GAT kernel (one warp per edge) --------------------
__global__ void edge_kernel(const int* __restrict__ row, const int* __restrict__ col,
                            const float* __restrict__ att,    // [NHEAD][128]
                            const float* __restrict__ gamma,  // [NHEAD]
                            const float* __restrict__ beta,   // [NHEAD]
                            int E)
{
    int e = (blockIdx.x * blockDim.x + threadIdx.x) >> 5;
    if (e >= E) return;
    const int l = threadIdx.x & 31;
    const int r = row[e], c = col[e];
    const float2* pr = (const float2*)(g_P + (size_t)r * HW);
    const float2* pc = (const float2*)(g_P + (size_t)c * HW);
    const float2* q  = (const float2*)(g_Q + (size_t)e * HW);
    const float2* at = (const float2*)att;   // head nh -> 64 float2

    float2 hj[NHEAD];
    float alpha[NHEAD];
#pragma unroll
    for (int nh = 0; nh < NHEAD; nh++) {
        float2 qv  = q[nh * 32 + l];
        float2 prv = pr[nh * 32 + l];
        float2 pcv = pc[nh * 32 + l];
        float hi0 = lrelu(prv.x + qv.x), hi1 = lrelu(prv.y + qv.y);
        float hj0 = lrelu(pcv.x + qv.x), hj1 = lrelu(pcv.y + qv.y);
        hj[nh].x = hj0; hj[nh].y = hj1;
        float2 a1 = at[nh * 64 + l];
        float2 a2 = at[nh * 64 + 32 + l];
        float part = hi0 * a1.x + hi1 * a1.y + hj0 * a2.x + hj1 * a2.y;
#pragma unroll
        for (int o = 16; o; o >>= 1) part += __shfl_xor_sync(0xffffffffu, part, o);
        alpha[nh] = part;
    }
    // lrelu -> groupnorm(eval) -> softmax over heads
    const float inv_std = 0.9999950000374997f;  // 1/sqrt(1+1e-5)
    float mx = -1e30f;
#pragma unroll
    for (int nh = 0; nh < NHEAD; nh++) {
        float a = lrelu(alpha[nh]);
        a = a * inv_std * gamma[nh] + beta[nh];
        alpha[nh] = a;
        mx = fmaxf(mx, a);
    }
    float s = 0.f;
#pragma unroll
    for (int nh = 0; nh < NHEAD; nh++) { float ev = expf(alpha[nh] - mx); alpha[nh] = ev; s += ev; }
    float inv = 0.1f / s;   // softmax normalizer * (1/NHEAD) head-mean
    float m0 = 0.f, m1 = 0.f;
#pragma unroll
    for (int nh = 0; nh < NHEAD; nh++) { m0 += hj[nh].x * alpha[nh]; m1 += hj[nh].y * alpha[nh]; }
    m0 *= inv; m1 *= inv;
    atomicAdd(&g_hagg[r * HD + 2 * l],     m0);
    atomicAdd(&g_hagg[r * HD + 2 * l + 1], m1);
}

// ---------------- node update ------------------------------------------------
__global__ void node_update(const float* __restrict__ b, int N, int first, int last)
{
    int idx = blockIdx.x * blockDim.x + threadIdx.x;
    if (idx >= N * HD) return;
    int k = idx & (HD - 1);
    float v = g_hagg[idx] + b[k];
    if (first) g_h[idx] = v;
    else       g_h[idx] = g_h[idx] + v;
    if (last)  g_h[idx] += g_h0[idx];
}

// ---------------- global-attention precompute: GB = gf @ W1[64:] + b1 --------
__global__ void gb_kernel(const float* __restrict__ gf, const float* __restrict__ W1,
                          const float* __restrict__ b1, int G)
{
    int g = blockIdx.x;
    int k = threadIdx.x;     // 64
    float acc = b1[k];
    const float* gr = gf + (size_t)g * GD;
    for (int j = 0; j < GD; j++) acc += gr[j] * W1[(64 + j) * HD + k];
    g_GB[g * HD + k] = acc;
}

// scores + segment max (warp per node)
__global__ void score_kernel(const int* __restrict__ batch,
                             const float* __restrict__ W1,
                             const float* __restrict__ W2, const float* __restrict__ b2,
                             int N)
{
    int n = (blockIdx.x * blockDim.x + threadIdx.x) >> 5;
    if (n >= N) return;
    int l = threadIdx.x & 31;
    int b = batch[n];
    int k0 = 2 * l;
    float s0 = g_GB[b * HD + k0], s1 = g_GB[b * HD + k0 + 1];
    const float* hr = g_h + (size_t)n * HD;
#pragma unroll 8
    for (int j = 0; j < HD; j++) {
        float hv = hr[j];
        s0 += hv * W1[j * HD + k0];
        s1 += hv * W1[j * HD + k0 + 1];
    }
    s0 = lrelu(s0); s1 = lrelu(s1);
    float part = s0 * W2[k0] + s1 * W2[k0 + 1];
#pragma unroll
    for (int o = 16; o; o >>= 1) part += __shfl_xor_sync(0xffffffffu, part, o);
    if (l == 0) {
        float sc = part + b2[0];
        g_score[n] = sc;
        atomicMax(&g_smax[b], f2o(sc));
    }
}

__global__ void exp_kernel(const int* __restrict__ batch, int N)
{
    int n = blockIdx.x * blockDim.x + threadIdx.x;
    if (n >= N) return;
    int b = batch[n];
    float ev = expf(g_score[n] - o2f(g_smax[b]));
    g_ex[n] = ev;
    atomicAdd(&g_denom[b], ev);
}

__global__ void pool_kernel(const int* __restrict__ batch, int N)
{
    int n = (blockIdx.x * blockDim.x + threadIdx.x) >> 5;
    if (n >= N) return;
    int l = threadIdx.x & 31;
    int b = batch[n];
    float w = g_ex[n] / g_denom[b];
    int k0 = 2 * l;
    atomicAdd(&g_pooled[b * HD + k0],     g_h[(size_t)n * HD + k0] * w);
    atomicAdd(&g_pooled[b * HD + k0 + 1], g_h[(size_t)n * HD + k0 + 1] * w);
}

__global__ void out_kernel(const float* __restrict__ W1, const float* __restrict__ b1,
                           const float* __restrict__ W2, const float* __restrict__ b2,
                           float* __restrict__ out)
{
    int g = blockIdx.x;
    int k = threadIdx.x;   // 64
    __shared__ float ps[HD];
    __shared__ float red[HD];
    ps[k] = g_pooled[g * HD + k];
    __syncthreads();
    float acc = b1[k];
#pragma unroll 8
    for (int j = 0; j < HD; j++) acc += ps[j] * W1[j * HD + k];
    acc = fmaxf(acc, 0.f);
    red[k] = acc * W2[k];
    __syncthreads();
    for (int o = 32; o; o >>= 1) {
        if (k < o) red[k] += red[k + o];
        __syncthreads();
    }
    if (k == 0) out[g] = red[0] + b2[0];
}

// ---------------- host launcher ---------------------------------------------
extern "C" void kernel_launch(void* const* d_in, const int* in_sizes, int n_in,
                              void* d_out, int out_size)
{
    const float* x      = (const float*)d_in[0];
    const int*   eidx   = (const int*)  d_in[1];
    const float* eattr  = (const float*)d_in[2];
    const int*   batch  = (const int*)  d_in[3];
    const float* gfeat  = (const float*)d_in[4];
    const float* node_W = (const float*)d_in[5];
    const float* node_b = (const float*)d_in[6];
    const float* edge_W = (const float*)d_in[7];
    const float* edge_b = (const float*)d_in[8];
    const float* conv_W = (const float*)d_in[9];
    const float* conv_att = (const float*)d_in[10];
    const float* conv_b = (const float*)d_in[11];
    const float* conv_g = (const float*)d_in[12];
    const float* conv_be = (const float*)d_in[13];
    const float* ga_W1  = (const float*)d_in[14];
    const float* ga_b1  = (const float*)d_in[15];
    const float* ga_W2  = (const float*)d_in[16];
    const float* ga_b2  = (const float*)d_in[17];
    const float* out_W1 = (const float*)d_in[18];
    const float* out_b1 = (const float*)d_in[19];
    const float* out_W2 = (const float*)d_in[20];
    const float* out_b2 = (const float*)d_in[21];

    const int N = in_sizes[3];
    const int E = in_sizes[2] / EF;
    const int G = in_sizes[4] / GD;

    const int* row = eidx;
    const int* col = eidx + E;

    float *p_h, *p_h0, *p_ea, *p_P, *p_Q, *p_hagg, *p_denom, *p_pooled;
    unsigned* p_smax;
    cudaGetSymbolAddress((void**)&p_h,     g_h);
    cudaGetSymbolAddress((void**)&p_h0,    g_h0);
    cudaGetSymbolAddress((void**)&p_ea,    g_ea);
    cudaGetSymbolAddress((void**)&p_P,     g_P);
    cudaGetSymbolAddress((void**)&p_Q,     g_Q);
    cudaGetSymbolAddress((void**)&p_hagg,  g_hagg);
    cudaGetSymbolAddress((void**)&p_smax,  g_smax);
    cudaGetSymbolAddress((void**)&p_denom, g_denom);
    cudaGetSymbolAddress((void**)&p_pooled,g_pooled);

    // embeddings
    {
        dim3 grid((N + 63) / 64, HD / 64);
        gemm_tiled<<<grid, 256>>>(x, NF, node_W, HD, node_b, p_h0, HD, N, NF, 1);
    }
    {
        dim3 grid((E + 63) / 64, HD / 64);
        gemm_tiled<<<grid, 256>>>(eattr, EF, edge_W, HD, edge_b, p_ea, HD, E, EF, 1);
    }

    const int nb1 = (N + 127) / 128;    // P row blocks
    const int nb2 = (E + 127) / 128;    // Q row blocks

    // GAT layers
    for (int i = 0; i < NL; i++) {
        const float* Wl   = conv_W + (size_t)i * 2 * HD * HW;  // [128][640]
        const float* Wtop = Wl;
        const float* Wbot = Wl + (size_t)HD * HW;
        const float* attL = conv_att + (size_t)i * NHEAD * 2 * HD;
        const float* bL   = conv_b + i * HD;
        const float* gmL  = conv_g + i * NHEAD;
        const float* btL  = conv_be + i * NHEAD;
        const float* Ain  = (i == 0) ? p_h0 : p_h;

        dim3 gridPQ(nb1 + nb2, HW / 128);
        gemm_pq<<<gridPQ, 256>>>(Ain, p_ea, Wtop, Wbot, p_P, p_Q, N, E, nb1);

        cudaMemsetAsync(p_hagg, 0, (size_t)N * HD * sizeof(float));

        int blocks = (E * 32 + 255) / 256;
        edge_kernel<<<blocks, 256>>>(row, col, attL, gmL, btL, E);

        node_update<<<(N * HD + 255) / 256, 256>>>(bL, N, i == 0, i == NL - 1);
    }

    // readout
    cudaMemsetAsync(p_smax, 0, G * sizeof(unsigned));
    cudaMemsetAsync(p_denom, 0, G * sizeof(float));
    cudaMemsetAsync(p_pooled, 0, (size_t)G * HD * sizeof(float));

    gb_kernel<<<G, HD>>>(gfeat, ga_W1, ga_b1, G);
    score_kernel<<<(N * 32 + 255) / 256, 256>>>(batch, ga_W1, ga_W2, ga_b2, N);
    exp_kernel<<<(N + 255) / 256, 256>>>(batch, N);
    pool_kernel<<<(N * 32 + 255) / 256, 256>>>(batch, N);
    out_kernel<<<G, HD>>>(out_W1, out_b1, out_W2, out_b2, (float*)d_out);
}

// round 11
// speedup vs baseline: 1.4424x; 1.4424x over previous
#include <cuda_runtime.h>
#include <cuda_bf16.h>
#include <math.h>
#include <stdint.h>

// Problem constants (match reference)
#define MAXN 10000
#define MAXE 40000
#define MAXG 128
#define NF 92
#define EF 50
#define HD 64
#define NHEAD 10
#define GD 108
#define NL 5
#define HW (NHEAD*HD)   // 640

// ---------------- static device scratch (no allocations allowed) -------------
__device__ float g_h[MAXN*HD];
__device__ float g_h0[MAXN*HD];
__device__ float g_ea[MAXE*HD];
__device__ float g_P[MAXN*HW];
__device__ float g_Q[(size_t)MAXE*HW];
__device__ float g_hagg[MAXN*HD];
__device__ float g_GB[MAXG*HD];
__device__ float g_score[MAXN];
__device__ float g_ex[MAXN];
__device__ unsigned g_smax[MAXG];
__device__ float g_denom[MAXG];
__device__ float g_pooled[MAXG*HD];
// bf16 split-precision operands
__device__ __nv_bfloat16 g_Whi[NL*2*HW*HD];   // [L*2][n=640][k=64]  (n-major)
__device__ __nv_bfloat16 g_Wlo[NL*2*HW*HD];
__device__ __nv_bfloat16 g_eahi[MAXE*HD];
__device__ __nv_bfloat16 g_ealo[MAXE*HD];
__device__ __nv_bfloat16 g_hhi[MAXN*HD];
__device__ __nv_bfloat16 g_hlo[MAXN*HD];

__device__ __forceinline__ float lrelu(float v) { return v > 0.f ? v : 0.2f * v; }

__device__ __forceinline__ unsigned f2o(float f) {
    unsigned u = __float_as_uint(f);
    return (u & 0x80000000u) ? ~u : (u | 0x80000000u);
}
__device__ __forceinline__ float o2f(unsigned u) {
    return (u & 0x80000000u) ? __uint_as_float(u ^ 0x80000000u) : __uint_as_float(~u);
}

// bf16 HMMA m16n8k16 (baseline mma.sync, works on sm_103 non-'a' target)
__device__ __forceinline__ void mma_bf16(float* c, const uint32_t* a, const uint32_t* b) {
    asm volatile(
        "mma.sync.aligned.m16n8k16.row.col.f32.bf16.bf16.f32 "
        "{%0,%1,%2,%3}, {%4,%5,%6,%7}, {%8,%9}, {%0,%1,%2,%3};"
        : "+f"(c[0]), "+f"(c[1]), "+f"(c[2]), "+f"(c[3])
        : "r"(a[0]), "r"(a[1]), "r"(a[2]), "r"(a[3]), "r"(b[0]), "r"(b[1]));
}

// ---------------- weight transpose + bf16 split (once per launch) ------------
// Wt[i*2+hf][n][k] = conv_W[i][hf*64+k][n], split into hi/lo bf16.
__global__ void prep_W(const float* __restrict__ W)
{
    int idx = blockIdx.x * blockDim.x + threadIdx.x;
    if (idx >= NL * 2 * HD * HW) return;
    int n  = idx % HW;
    int t  = idx / HW;
    int k  = t % HD;
    int t2 = t / HD;          // i*2+hf
    float v = W[((size_t)t2 * HD + k) * HW + n];
    __nv_bfloat16 hi = __float2bfloat16(v);
    float r = v - __bfloat162float(hi);
    size_t o = ((size_t)t2 * HW + n) * HD + k;
    g_Whi[o] = hi;
    g_Wlo[o] = __float2bfloat16(r);
}

// fp32 -> bf16 hi/lo elementwise split
__global__ void split_bf16(const float* __restrict__ src,
                           __nv_bfloat16* __restrict__ hi,
                           __nv_bfloat16* __restrict__ lo, int n)
{
    int i = blockIdx.x * blockDim.x + threadIdx.x;
    if (i >= n) return;
    float v = src[i];
    __nv_bfloat16 h = __float2bfloat16(v);
    float r = v - __bfloat162float(h);
    hi[i] = h;
    lo[i] = __float2bfloat16(r);
}

// ---------------- tensor-core (HMMA) fused P/Q GEMM --------------------------
// C[M,640] = A[M,64] @ W[64,640]; split-bf16 3-term; fp32 accum.
// CTA: 256 threads = 8 warps; CTA tile 128(m) x 128(n).
// Warp tile 32(m) x 64(n): 2 m-frags x 8 n-frags of m16n8k16, K=64 in 4 steps.
// No smem: operands LDG'd per-lane from L2-resident arrays.
__global__ __launch_bounds__(256)
void gemm_mma(const __nv_bfloat16* __restrict__ A1h, const __nv_bfloat16* __restrict__ A1l,
              const __nv_bfloat16* __restrict__ A2h, const __nv_bfloat16* __restrict__ A2l,
              const __nv_bfloat16* __restrict__ W1h, const __nv_bfloat16* __restrict__ W1l,
              const __nv_bfloat16* __restrict__ W2h, const __nv_bfloat16* __restrict__ W2l,
              float* __restrict__ C1, float* __restrict__ C2,
              int M1, int M2, int nb1)
{
    const __nv_bfloat16 *ah, *al, *wh, *wl; float* C; int M, row0;
    if ((int)blockIdx.x < nb1) {
        ah = A1h; al = A1l; wh = W1h; wl = W1l; C = C1; M = M1;
        row0 = blockIdx.x * 128;
    } else {
        ah = A2h; al = A2l; wh = W2h; wl = W2l; C = C2; M = M2;
        row0 = (blockIdx.x - nb1) * 128;
    }
    const int col0 = blockIdx.y * 128;

    const int wid  = threadIdx.x >> 5;
    const int lane = threadIdx.x & 31;
    const int g    = lane >> 2;      // 0..7
    const int tig  = lane & 3;       // 0..3

    const int warp_m = wid & 3;      // 0..3 -> 32 rows each
    const int warp_n = wid >> 2;     // 0..1 -> 64 cols each

    float acc[2][8][4];
#pragma unroll
    for (int mf = 0; mf < 2; mf++)
#pragma unroll
        for (int nf = 0; nf < 8; nf++)
#pragma unroll
            for (int j = 0; j < 4; j++) acc[mf][nf][j] = 0.f;

    // Row indices (clamped; OOB rows never stored)
    int rA[2][2];
#pragma unroll
    for (int mf = 0; mf < 2; mf++) {
        int base = row0 + warp_m * 32 + mf * 16 + g;
        rA[mf][0] = min(base,     M - 1);
        rA[mf][1] = min(base + 8, M - 1);
    }
    // Column indices for B frags
    int nB[8];
#pragma unroll
    for (int nf = 0; nf < 8; nf++) nB[nf] = col0 + warp_n * 64 + nf * 8 + g;

#pragma unroll
    for (int ks = 0; ks < 4; ks++) {
        const int k0 = ks * 16;
        // ---- A fragments (hi & lo), 2 m-frags ----
        uint32_t Ah[2][4], Al[2][4];
#pragma unroll
        for (int mf = 0; mf < 2; mf++) {
            const int o0 = rA[mf][0] * HD + k0 + 2 * tig;
            const int o1 = rA[mf][1] * HD + k0 + 2 * tig;
            Ah[mf][0] = *(const uint32_t*)(ah + o0);
            Ah[mf][1] = *(const uint32_t*)(ah + o1);
            Ah[mf][2] = *(const uint32_t*)(ah + o0 + 8);
            Ah[mf][3] = *(const uint32_t*)(ah + o1 + 8);
            Al[mf][0] = *(const uint32_t*)(al + o0);
            Al[mf][1] = *(const uint32_t*)(al + o1);
            Al[mf][2] = *(const uint32_t*)(al + o0 + 8);
            Al[mf][3] = *(const uint32_t*)(al + o1 + 8);
        }
        // ---- B fragments (hi & lo), 8 n-frags ----
        uint32_t Bh[8][2], Bl[8][2];
#pragma unroll
        for (int nf = 0; nf < 8; nf++) {
            const int o = nB[nf] * HD + k0 + 2 * tig;
            Bh[nf][0] = *(const uint32_t*)(wh + o);
            Bh[nf][1] = *(const uint32_t*)(wh + o + 8);
            Bl[nf][0] = *(const uint32_t*)(wl + o);
            Bl[nf][1] = *(const uint32_t*)(wl + o + 8);
        }
        // ---- 3-term MMAs ----
#pragma unroll
        for (int mf = 0; mf < 2; mf++)
#pragma unroll
            for (int nf = 0; nf < 8; nf++) {
                mma_bf16(acc[mf][nf], Ah[mf], Bh[nf]);
                mma_bf16(acc[mf][nf], Ah[mf], Bl[nf]);
                mma_bf16(acc[mf][nf], Al[mf], Bh[nf]);
            }
    }

    // ---- store ----
#pragma unroll
    for (int mf = 0; mf < 2; mf++) {
        const int r0 = row0 + warp_m * 32 + mf * 16 + g;
#pragma unroll
        for (int nf = 0; nf < 8; nf++) {
            const int c = col0 + warp_n * 64 + nf * 8 + 2 * tig;
            if (r0 < M) {
                float2 v = make_float2(acc[mf][nf][0], acc[mf][nf][1]);
                *(float2*)(C + (size_t)r0 * HW + c) = v;
            }
            if (r0 + 8 < M) {
                float2 v = make_float2(acc[mf][nf][2], acc[mf][nf][3]);
                *(float2*)(C + (size_t)(r0 + 8) * HW + c) = v;
            }
        }
    }
}

// ---------------- tiled fp32 GEMM (embeddings) -------------------------------
__global__ void gemm_tiled(const float* __restrict__ A, int lda,
                           const float* __restrict__ W, int ldw,
                           const float* __restrict__ bias,
                           float* __restrict__ C, int ldc,
                           int M, int K, int act)
{
    __shared__ float As[16][64];
    __shared__ float Ws[16][64];
    const int row0 = blockIdx.x * 64;
    const int col0 = blockIdx.y * 64;
    const int tid = threadIdx.x;
    const int tx = tid & 15, ty = tid >> 4;

    float acc[4][4];
#pragma unroll
    for (int i = 0; i < 4; i++)
#pragma unroll
        for (int j = 0; j < 4; j++) acc[i][j] = 0.f;

    for (int k0 = 0; k0 < K; k0 += 16) {
#pragma unroll
        for (int i = 0; i < 4; i++) {
            int e = tid + 256 * i;
            int r = e >> 4, kk = e & 15;
            int gr = row0 + r, gk = k0 + kk;
            As[kk][r] = (gr < M && gk < K) ? A[(size_t)gr * lda + gk] : 0.f;
        }
#pragma unroll
        for (int i = 0; i < 4; i++) {
            int e = tid + 256 * i;
            int kk = e >> 6, c = e & 63;
            int gk = k0 + kk;
            Ws[kk][c] = (gk < K) ? W[(size_t)gk * ldw + col0 + c] : 0.f;
        }
        __syncthreads();
#pragma unroll
        for (int kk = 0; kk < 16; kk++) {
            float4 a = *(const float4*)&As[kk][ty * 4];
            float4 b = *(const float4*)&Ws[kk][tx * 4];
            float av[4] = {a.x, a.y, a.z, a.w};
            float bv[4] = {b.x, b.y, b.z, b.w};
#pragma unroll
            for (int i = 0; i < 4; i++)
#pragma unroll
                for (int j = 0; j < 4; j++) acc[i][j] += av[i] * bv[j];
        }
        __syncthreads();
    }
#pragma unroll
    for (int i = 0; i < 4; i++) {
        int r = row0 + ty * 4 + i;
        if (r >= M) continue;
#pragma unroll
        for (int j = 0; j < 4; j++) {
            int c = col0 + tx * 4 + j;
            float v = acc[i][j];
            if (bias) v += bias[c];
            if (act) v = lrelu(v);
            C[(size_t)r * ldc + c] = v;
        }
    }
}

// ---------------- per-edge GAT kernel (one warp per edge) --------------------
__global__ void edge_kernel(const int* __restrict__ row, const int* __restrict__ col,
                            const float* __restrict__ att,
                            const float* __restrict__ gamma,
                            const float* __restrict__ beta,
                            int E)
{
    int e = (blockIdx.x * blockDim.x + threadIdx.x) >> 5;
    if (e >= E) return;
    const int l = threadIdx.x & 31;
    const int r = row[e], c = col[e];
    const float2* pr = (const float2*)(g_P + (size_t)r * HW);
    const float2* pc = (const float2*)(g_P + (size_t)c * HW);
    const float2* q  = (const float2*)(g_Q + (size_t)e * HW);
    const float2* at = (const float2*)att;

    float2 hj[NHEAD];
    float alpha[NHEAD];
#pragma unroll
    for (int nh = 0; nh < NHEAD; nh++) {
        float2 qv  = q[nh * 32 + l];
        float2 prv = pr[nh * 32 + l];
        float2 pcv = pc[nh * 32 + l];
        float hi0 = lrelu(prv.x + qv.x), hi1 = lrelu(prv.y + qv.y);
        float hj0 = lrelu(pcv.x + qv.x), hj1 = lrelu(pcv.y + qv.y);
        hj[nh].x = hj0; hj[nh].y = hj1;
        float2 a1 = at[nh * 64 + l];
        float2 a2 = at[nh * 64 + 32 + l];
        float part = hi0 * a1.x + hi1 * a1.y + hj0 * a2.x + hj1 * a2.y;
#pragma unroll
        for (int o = 16; o; o >>= 1) part += __shfl_xor_sync(0xffffffffu, part, o);
        alpha[nh] = part;
    }
    const float inv_std = 0.9999950000374997f;  // 1/sqrt(1+1e-5)
    float mx = -1e30f;
#pragma unroll
    for (int nh = 0; nh < NHEAD; nh++) {
        float a = lrelu(alpha[nh]);
        a = a * inv_std * gamma[nh] + beta[nh];
        alpha[nh] = a;
        mx = fmaxf(mx, a);
    }
    float s = 0.f;
#pragma unroll
    for (int nh = 0; nh < NHEAD; nh++) { float ev = expf(alpha[nh] - mx); alpha[nh] = ev; s += ev; }
    float inv = 0.1f / s;
    float m0 = 0.f, m1 = 0.f;
#pragma unroll
    for (int nh = 0; nh < NHEAD; nh++) { m0 += hj[nh].x * alpha[nh]; m1 += hj[nh].y * alpha[nh]; }
    m0 *= inv; m1 *= inv;
    atomicAdd(&g_hagg[r * HD + 2 * l],     m0);
    atomicAdd(&g_hagg[r * HD + 2 * l + 1], m1);
}

// ---------------- node update ------------------------------------------------
__global__ void node_update(const float* __restrict__ b, int N, int first, int last)
{
    int idx = blockIdx.x * blockDim.x + threadIdx.x;
    if (idx >= N * HD) return;
    int k = idx & (HD - 1);
    float v = g_hagg[idx] + b[k];
    if (first) g_h[idx] = v;
    else       g_h[idx] = g_h[idx] + v;
    if (last)  g_h[idx] += g_h0[idx];
}

// ---------------- readout ----------------------------------------------------
__global__ void gb_kernel(const float* __restrict__ gf, const float* __restrict__ W1,
                          const float* __restrict__ b1, int G)
{
    int g = blockIdx.x;
    int k = threadIdx.x;
    float acc = b1[k];
    const float* gr = gf + (size_t)g * GD;
    for (int j = 0; j < GD; j++) acc += gr[j] * W1[(64 + j) * HD + k];
    g_GB[g * HD + k] = acc;
}

__global__ void score_kernel(const int* __restrict__ batch,
                             const float* __restrict__ W1,
                             const float* __restrict__ W2, const float* __restrict__ b2,
                             int N)
{
    int n = (blockIdx.x * blockDim.x + threadIdx.x) >> 5;
    if (n >= N) return;
    int l = threadIdx.x & 31;
    int b = batch[n];
    int k0 = 2 * l;
    float s0 = g_GB[b * HD + k0], s1 = g_GB[b * HD + k0 + 1];
    const float* hr = g_h + (size_t)n * HD;
#pragma unroll 8
    for (int j = 0; j < HD; j++) {
        float hv = hr[j];
        s0 += hv * W1[j * HD + k0];
        s1 += hv * W1[j * HD + k0 + 1];
    }
    s0 = lrelu(s0); s1 = lrelu(s1);
    float part = s0 * W2[k0] + s1 * W2[k0 + 1];
#pragma unroll
    for (int o = 16; o; o >>= 1) part += __shfl_xor_sync(0xffffffffu, part, o);
    if (l == 0) {
        float sc = part + b2[0];
        g_score[n] = sc;
        atomicMax(&g_smax[b], f2o(sc));
    }
}

__global__ void exp_kernel(const int* __restrict__ batch, int N)
{
    int n = blockIdx.x * blockDim.x + threadIdx.x;
    if (n >= N) return;
    int b = batch[n];
    float ev = expf(g_score[n] - o2f(g_smax[b]));
    g_ex[n] = ev;
    atomicAdd(&g_denom[b], ev);
}

__global__ void pool_kernel(const int* __restrict__ batch, int N)
{
    int n = (blockIdx.x * blockDim.x + threadIdx.x) >> 5;
    if (n >= N) return;
    int l = threadIdx.x & 31;
    int b = batch[n];
    float w = g_ex[n] / g_denom[b];
    int k0 = 2 * l;
    atomicAdd(&g_pooled[b * HD + k0],     g_h[(size_t)n * HD + k0] * w);
    atomicAdd(&g_pooled[b * HD + k0 + 1], g_h[(size_t)n * HD + k0 + 1] * w);
}

__global__ void out_kernel(const float* __restrict__ W1, const float* __restrict__ b1,
                           const float* __restrict__ W2, const float* __restrict__ b2,
                           float* __restrict__ out)
{
    int g = blockIdx.x;
    int k = threadIdx.x;
    __shared__ float ps[HD];
    __shared__ float red[HD];
    ps[k] = g_pooled[g * HD + k];
    __syncthreads();
    float acc = b1[k];
#pragma unroll 8
    for (int j = 0; j < HD; j++) acc += ps[j] * W1[j * HD + k];
    acc = fmaxf(acc, 0.f);
    red[k] = acc * W2[k];
    __syncthreads();
    for (int o = 32; o; o >>= 1) {
        if (k < o) red[k] += red[k + o];
        __syncthreads();
    }
    if (k == 0) out[g] = red[0] + b2[0];
}

// ---------------- host launcher ---------------------------------------------
extern "C" void kernel_launch(void* const* d_in, const int* in_sizes, int n_in,
                              void* d_out, int out_size)
{
    const float* x      = (const float*)d_in[0];
    const int*   eidx   = (const int*)  d_in[1];
    const float* eattr  = (const float*)d_in[2];
    const int*   batch  = (const int*)  d_in[3];
    const float* gfeat  = (const float*)d_in[4];
    const float* node_W = (const float*)d_in[5];
    const float* node_b = (const float*)d_in[6];
    const float* edge_W = (const float*)d_in[7];
    const float* edge_b = (const float*)d_in[8];
    const float* conv_W = (const float*)d_in[9];
    const float* conv_att = (const float*)d_in[10];
    const float* conv_b = (const float*)d_in[11];
    const float* conv_g = (const float*)d_in[12];
    const float* conv_be = (const float*)d_in[13];
    const float* ga_W1  = (const float*)d_in[14];
    const float* ga_b1  = (const float*)d_in[15];
    const float* ga_W2  = (const float*)d_in[16];
    const float* ga_b2  = (const float*)d_in[17];
    const float* out_W1 = (const float*)d_in[18];
    const float* out_b1 = (const float*)d_in[19];
    const float* out_W2 = (const float*)d_in[20];
    const float* out_b2 = (const float*)d_in[21];

    const int N = in_sizes[3];
    const int E = in_sizes[2] / EF;
    const int G = in_sizes[4] / GD;

    const int* row = eidx;
    const int* col = eidx + E;

    float *p_h, *p_h0, *p_ea, *p_P, *p_Q, *p_hagg, *p_denom, *p_pooled;
    unsigned* p_smax;
    __nv_bfloat16 *p_Whi, *p_Wlo, *p_eahi, *p_ealo, *p_hhi, *p_hlo;
    cudaGetSymbolAddress((void**)&p_h,     g_h);
    cudaGetSymbolAddress((void**)&p_h0,    g_h0);
    cudaGetSymbolAddress((void**)&p_ea,    g_ea);
    cudaGetSymbolAddress((void**)&p_P,     g_P);
    cudaGetSymbolAddress((void**)&p_Q,     g_Q);
    cudaGetSymbolAddress((void**)&p_hagg,  g_hagg);
    cudaGetSymbolAddress((void**)&p_smax,  g_smax);
    cudaGetSymbolAddress((void**)&p_denom, g_denom);
    cudaGetSymbolAddress((void**)&p_pooled,g_pooled);
    cudaGetSymbolAddress((void**)&p_Whi,   g_Whi);
    cudaGetSymbolAddress((void**)&p_Wlo,   g_Wlo);
    cudaGetSymbolAddress((void**)&p_eahi,  g_eahi);
    cudaGetSymbolAddress((void**)&p_ealo,  g_ealo);
    cudaGetSymbolAddress((void**)&p_hhi,   g_hhi);
    cudaGetSymbolAddress((void**)&p_hlo,   g_hlo);

    // embeddings (fp32)
    {
        dim3 grid((N + 63) / 64, HD / 64);
        gemm_tiled<<<grid, 256>>>(x, NF, node_W, HD, node_b, p_h0, HD, N, NF, 1);
    }
    {
        dim3 grid((E + 63) / 64, HD / 64);
        gemm_tiled<<<grid, 256>>>(eattr, EF, edge_W, HD, edge_b, p_ea, HD, E, EF, 1);
    }

    // prep: transpose+split conv weights; split edge embedding (constant across layers)
    prep_W<<<(NL * 2 * HD * HW + 255) / 256, 256>>>(conv_W);
    split_bf16<<<(E * HD + 255) / 256, 256>>>(p_ea, p_eahi, p_ealo, E * HD);

    const int nb1 = (N + 127) / 128;
    const int nb2 = (E + 127) / 128;

    for (int i = 0; i < NL; i++) {
        const float* attL = conv_att + (size_t)i * NHEAD * 2 * HD;
        const float* bL   = conv_b + i * HD;
        const float* gmL  = conv_g + i * NHEAD;
        const float* btL  = conv_be + i * NHEAD;
        const float* Ain  = (i == 0) ? p_h0 : p_h;

        split_bf16<<<(N * HD + 255) / 256, 256>>>(Ain, p_hhi, p_hlo, N * HD);

        const __nv_bfloat16* WPh = p_Whi + (size_t)(i * 2 + 0) * HW * HD;
        const __nv_bfloat16* WPl = p_Wlo + (size_t)(i * 2 + 0) * HW * HD;
        const __nv_bfloat16* WQh = p_Whi + (size_t)(i * 2 + 1) * HW * HD;
        const __nv_bfloat16* WQl = p_Wlo + (size_t)(i * 2 + 1) * HW * HD;

        dim3 gridPQ(nb1 + nb2, HW / 128);
        gemm_mma<<<gridPQ, 256>>>(p_hhi, p_hlo, p_eahi, p_ealo,
                                  WPh, WPl, WQh, WQl,
                                  p_P, p_Q, N, E, nb1);

        cudaMemsetAsync(p_hagg, 0, (size_t)N * HD * sizeof(float));

        int blocks = (E * 32 + 255) / 256;
        edge_kernel<<<blocks, 256>>>(row, col, attL, gmL, btL, E);

        node_update<<<(N * HD + 255) / 256, 256>>>(bL, N, i == 0, i == NL - 1);
    }

    // readout
    cudaMemsetAsync(p_smax, 0, G * sizeof(unsigned));
    cudaMemsetAsync(p_denom, 0, G * sizeof(float));
    cudaMemsetAsync(p_pooled, 0, (size_t)G * HD * sizeof(float));

    gb_kernel<<<G, HD>>>(gfeat, ga_W1, ga_b1, G);
    score_kernel<<<(N * 32 + 255) / 256, 256>>>(batch, ga_W1, ga_W2, ga_b2, N);
    exp_kernel<<<(N + 255) / 256, 256>>>(batch, N);
    pool_kernel<<<(N * 32 + 255) / 256, 256>>>(batch, N);
    out_kernel<<<G, HD>>>(out_W1, out_b1, out_W2, out_b2, (float*)d_out);
}

// round 12
// speedup vs baseline: 1.7898x; 1.2408x over previous
#include <cuda_runtime.h>
#include <cuda_bf16.h>
#include <math.h>
#include <stdint.h>

// Problem constants (match reference)
#define MAXN 10000
#define MAXE 40000
#define MAXG 128
#define NF 92
#define EF 50
#define HD 64
#define NHEAD 10
#define GD 108
#define NL 5
#define HW (NHEAD*HD)   // 640

// ---------------- static device scratch (no allocations allowed) -------------
__device__ float g_h[MAXN*HD];
__device__ float g_h0[MAXN*HD];
__device__ float g_ea[MAXE*HD];
__device__ float g_P[MAXN*HW];
__device__ float g_Q[(size_t)MAXE*HW];
__device__ float g_hagg[MAXN*HD];
__device__ float g_GB[MAXG*HD];
__device__ float g_score[MAXN];
__device__ float g_ex[MAXN];
__device__ unsigned g_smax[MAXG];
__device__ float g_denom[MAXG];
__device__ float g_pooled[MAXG*HD];
// tf32 operands (fp32 storage, tf32-rounded, fragment-pair-permuted layout)
__device__ float g_Wt[NL*2*HW*HD];   // [L*2][n=640][j=64]
__device__ float g_eat[MAXE*HD];
__device__ float g_ht[MAXN*HD];

__device__ __forceinline__ float lrelu(float v) { return v > 0.f ? v : 0.2f * v; }

__device__ __forceinline__ unsigned f2o(float f) {
    unsigned u = __float_as_uint(f);
    return (u & 0x80000000u) ? ~u : (u | 0x80000000u);
}
__device__ __forceinline__ float o2f(unsigned u) {
    return (u & 0x80000000u) ? __uint_as_float(u ^ 0x80000000u) : __uint_as_float(~u);
}

__device__ __forceinline__ float tf32_rnd(float v) {
    uint32_t r;
    asm("cvt.rna.tf32.f32 %0, %1;" : "=r"(r) : "f"(v));
    return __uint_as_float(r);
}

// fragment-pair permutation: position j in a row holds original k-index:
//   ks = j>>3, r = j&7, tig = r>>1, half = r&1  ->  k = ks*8 + tig + half*4
// so that lane (g,tig)'s two frag elements (k0+tig, k0+tig+4) are adjacent (LDG.64).
__device__ __forceinline__ int orig_col(int j) {
    int ks = j >> 3, r = j & 7;
    return ks * 8 + (r >> 1) + (r & 1) * 4;
}

// tf32 HMMA m16n8k8 (baseline mma.sync; supported on sm_103 non-'a' target)
__device__ __forceinline__ void mma_tf32(float* c, const uint32_t* a, const uint32_t* b) {
    asm volatile(
        "mma.sync.aligned.m16n8k8.row.col.f32.tf32.tf32.f32 "
        "{%0,%1,%2,%3}, {%4,%5,%6,%7}, {%8,%9}, {%0,%1,%2,%3};"
        : "+f"(c[0]), "+f"(c[1]), "+f"(c[2]), "+f"(c[3])
        : "r"(a[0]), "r"(a[1]), "r"(a[2]), "r"(a[3]), "r"(b[0]), "r"(b[1]));
}

// ---------------- prep kernels ----------------------------------------------
// Wt[t2][n][j] = tf32( conv_W[t2*64 + orig_col(j)][n] ), t2 = layer*2 + {top,bot}
__global__ void prep_W(const float* __restrict__ W)
{
    int idx = blockIdx.x * blockDim.x + threadIdx.x;
    if (idx >= NL * 2 * HW * HD) return;
    int j  = idx & 63;
    int t  = idx >> 6;
    int n  = t % HW;
    int t2 = t / HW;
    float v = W[((size_t)t2 * HD + orig_col(j)) * HW + n];
    g_Wt[((size_t)t2 * HW + n) * HD + j] = tf32_rnd(v);
}

// dst[row][j] = tf32( src[row][orig_col(j)] )
__global__ void round_perm(const float* __restrict__ src, float* __restrict__ dst, int n)
{
    int idx = blockIdx.x * blockDim.x + threadIdx.x;
    if (idx >= n) return;
    int j = idx & 63;
    int row = idx >> 6;
    dst[idx] = tf32_rnd(src[row * HD + orig_col(j)]);
}

// ---------------- tf32 HMMA fused P/Q GEMM -----------------------------------
// C[M,640] = A[M,64] @ W[64,640]; tf32 single-term; fp32 accum.
// CTA 256 thr = 8 warps; tile 128x128; warp tile 32x64 (2 mf x 8 nf), K=64 in 8 ks.
// Operands LDG.64'd directly from permuted global arrays (L2-resident).
__global__ __launch_bounds__(256)
void gemm_mma(const float* __restrict__ A1, const float* __restrict__ A2,
              const float* __restrict__ W1, const float* __restrict__ W2,
              float* __restrict__ C1, float* __restrict__ C2,
              int M1, int M2, int nb1)
{
    const float *A, *W; float* C; int M, row0;
    if ((int)blockIdx.x < nb1) {
        A = A1; W = W1; C = C1; M = M1; row0 = blockIdx.x * 128;
    } else {
        A = A2; W = W2; C = C2; M = M2; row0 = (blockIdx.x - nb1) * 128;
    }
    const int col0 = blockIdx.y * 128;

    const int wid  = threadIdx.x >> 5;
    const int lane = threadIdx.x & 31;
    const int g    = lane >> 2;      // 0..7
    const int tig  = lane & 3;       // 0..3

    const int warp_m = wid & 3;      // 32 rows each
    const int warp_n = wid >> 2;     // 64 cols each

    float acc[2][8][4];
#pragma unroll
    for (int mf = 0; mf < 2; mf++)
#pragma unroll
        for (int nf = 0; nf < 8; nf++)
#pragma unroll
            for (int j = 0; j < 4; j++) acc[mf][nf][j] = 0.f;

    int rA[2][2];
#pragma unroll
    for (int mf = 0; mf < 2; mf++) {
        int base = row0 + warp_m * 32 + mf * 16 + g;
        rA[mf][0] = min(base,     M - 1);
        rA[mf][1] = min(base + 8, M - 1);
    }
    int nB[8];
#pragma unroll
    for (int nf = 0; nf < 8; nf++) nB[nf] = col0 + warp_n * 64 + nf * 8 + g;

#pragma unroll
    for (int ks = 0; ks < 8; ks++) {
        const int kofs = ks * 8 + tig * 2;
        uint32_t Afrag[2][4];
#pragma unroll
        for (int mf = 0; mf < 2; mf++) {
            uint2 v0 = *(const uint2*)(A + rA[mf][0] * HD + kofs);  // (a0, a2)
            uint2 v1 = *(const uint2*)(A + rA[mf][1] * HD + kofs);  // (a1, a3)
            Afrag[mf][0] = v0.x; Afrag[mf][2] = v0.y;
            Afrag[mf][1] = v1.x; Afrag[mf][3] = v1.y;
        }
        uint32_t Bfrag[8][2];
#pragma unroll
        for (int nf = 0; nf < 8; nf++) {
            uint2 v = *(const uint2*)(W + nB[nf] * HD + kofs);      // (b0, b1)
            Bfrag[nf][0] = v.x; Bfrag[nf][1] = v.y;
        }
#pragma unroll
        for (int mf = 0; mf < 2; mf++)
#pragma unroll
            for (int nf = 0; nf < 8; nf++)
                mma_tf32(acc[mf][nf], Afrag[mf], Bfrag[nf]);
    }

    // store
#pragma unroll
    for (int mf = 0; mf < 2; mf++) {
        const int r0 = row0 + warp_m * 32 + mf * 16 + g;
#pragma unroll
        for (int nf = 0; nf < 8; nf++) {
            const int c = col0 + warp_n * 64 + nf * 8 + 2 * tig;
            if (r0 < M) {
                float2 v = make_float2(acc[mf][nf][0], acc[mf][nf][1]);
                *(float2*)(C + (size_t)r0 * HW + c) = v;
            }
            if (r0 + 8 < M) {
                float2 v = make_float2(acc[mf][nf][2], acc[mf][nf][3]);
                *(float2*)(C + (size_t)(r0 + 8) * HW + c) = v;
            }
        }
    }
}

// ---------------- tiled fp32 GEMM (embeddings) -------------------------------
__global__ void gemm_tiled(const float* __restrict__ A, int lda,
                           const float* __restrict__ W, int ldw,
                           const float* __restrict__ bias,
                           float* __restrict__ C, int ldc,
                           int M, int K, int act)
{
    __shared__ float As[16][64];
    __shared__ float Ws[16][64];
    const int row0 = blockIdx.x * 64;
    const int col0 = blockIdx.y * 64;
    const int tid = threadIdx.x;
    const int tx = tid & 15, ty = tid >> 4;

    float acc[4][4];
#pragma unroll
    for (int i = 0; i < 4; i++)
#pragma unroll
        for (int j = 0; j < 4; j++) acc[i][j] = 0.f;

    for (int k0 = 0; k0 < K; k0 += 16) {
#pragma unroll
        for (int i = 0; i < 4; i++) {
            int e = tid + 256 * i;
            int r = e >> 4, kk = e & 15;
            int gr = row0 + r, gk = k0 + kk;
            As[kk][r] = (gr < M && gk < K) ? A[(size_t)gr * lda + gk] : 0.f;
        }
#pragma unroll
        for (int i = 0; i < 4; i++) {
            int e = tid + 256 * i;
            int kk = e >> 6, c = e & 63;
            int gk = k0 + kk;
            Ws[kk][c] = (gk < K) ? W[(size_t)gk * ldw + col0 + c] : 0.f;
        }
        __syncthreads();
#pragma unroll
        for (int kk = 0; kk < 16; kk++) {
            float4 a = *(const float4*)&As[kk][ty * 4];
            float4 b = *(const float4*)&Ws[kk][tx * 4];
            float av[4] = {a.x, a.y, a.z, a.w};
            float bv[4] = {b.x, b.y, b.z, b.w};
#pragma unroll
            for (int i = 0; i < 4; i++)
#pragma unroll
                for (int j = 0; j < 4; j++) acc[i][j] += av[i] * bv[j];
        }
        __syncthreads();
    }
#pragma unroll
    for (int i = 0; i < 4; i++) {
        int r = row0 + ty * 4 + i;
        if (r >= M) continue;
#pragma unroll
        for (int j = 0; j < 4; j++) {
            int c = col0 + tx * 4 + j;
            float v = acc[i][j];
            if (bias) v += bias[c];
            if (act) v = lrelu(v);
            C[(size_t)r * ldc + c] = v;
        }
    }
}

// ---------------- per-edge GAT kernel (one warp per edge) --------------------
__global__ void edge_kernel(const int* __restrict__ row, const int* __restrict__ col,
                            const float* __restrict__ att,
                            const float* __restrict__ gamma,
                            const float* __restrict__ beta,
                            int E)
{
    int e = (blockIdx.x * blockDim.x + threadIdx.x) >> 5;
    if (e >= E) return;
    const int l = threadIdx.x & 31;
    const int r = row[e], c = col[e];
    const float2* pr = (const float2*)(g_P + (size_t)r * HW);
    const float2* pc = (const float2*)(g_P + (size_t)c * HW);
    const float2* q  = (const float2*)(g_Q + (size_t)e * HW);
    const float2* at = (const float2*)att;

    float2 hj[NHEAD];
    float alpha[NHEAD];
#pragma unroll
    for (int nh = 0; nh < NHEAD; nh++) {
        float2 qv  = q[nh * 32 + l];
        float2 prv = pr[nh * 32 + l];
        float2 pcv = pc[nh * 32 + l];
        float hi0 = lrelu(prv.x + qv.x), hi1 = lrelu(prv.y + qv.y);
        float hj0 = lrelu(pcv.x + qv.x), hj1 = lrelu(pcv.y + qv.y);
        hj[nh].x = hj0; hj[nh].y = hj1;
        float2 a1 = at[nh * 64 + l];
        float2 a2 = at[nh * 64 + 32 + l];
        float part = hi0 * a1.x + hi1 * a1.y + hj0 * a2.x + hj1 * a2.y;
#pragma unroll
        for (int o = 16; o; o >>= 1) part += __shfl_xor_sync(0xffffffffu, part, o);
        alpha[nh] = part;
    }
    const float inv_std = 0.9999950000374997f;  // 1/sqrt(1+1e-5)
    float mx = -1e30f;
#pragma unroll
    for (int nh = 0; nh < NHEAD; nh++) {
        float a = lrelu(alpha[nh]);
        a = a * inv_std * gamma[nh] + beta[nh];
        alpha[nh] = a;
        mx = fmaxf(mx, a);
    }
    float s = 0.f;
#pragma unroll
    for (int nh = 0; nh < NHEAD; nh++) { float ev = expf(alpha[nh] - mx); alpha[nh] = ev; s += ev; }
    float inv = 0.1f / s;
    float m0 = 0.f, m1 = 0.f;
#pragma unroll
    for (int nh = 0; nh < NHEAD; nh++) { m0 += hj[nh].x * alpha[nh]; m1 += hj[nh].y * alpha[nh]; }
    m0 *= inv; m1 *= inv;
    atomicAdd(&g_hagg[r * HD + 2 * l],     m0);
    atomicAdd(&g_hagg[r * HD + 2 * l + 1], m1);
}

// ---------------- node update ------------------------------------------------
__global__ void node_update(const float* __restrict__ b, int N, int first, int last)
{
    int idx = blockIdx.x * blockDim.x + threadIdx.x;
    if (idx >= N * HD) return;
    int k = idx & (HD - 1);
    float v = g_hagg[idx] + b[k];
    if (first) g_h[idx] = v;
    else       g_h[idx] = g_h[idx] + v;
    if (last)  g_h[idx] += g_h0[idx];
}

// ---------------- readout ----------------------------------------------------
__global__ void gb_kernel(const float* __restrict__ gf, const float* __restrict__ W1,
                          const float* __restrict__ b1, int G)
{
    int g = blockIdx.x;
    int k = threadIdx.x;
    float acc = b1[k];
    const float* gr = gf + (size_t)g * GD;
    for (int j = 0; j < GD; j++) acc += gr[j] * W1[(64 + j) * HD + k];
    g_GB[g * HD + k] = acc;
}

__global__ void score_kernel(const int* __restrict__ batch,
                             const float* __restrict__ W1,
                             const float* __restrict__ W2, const float* __restrict__ b2,
                             int N)
{
    int n = (blockIdx.x * blockDim.x + threadIdx.x) >> 5;
    if (n >= N) return;
    int l = threadIdx.x & 31;
    int b = batch[n];
    int k0 = 2 * l;
    float s0 = g_GB[b * HD + k0], s1 = g_GB[b * HD + k0 + 1];
    const float* hr = g_h + (size_t)n * HD;
#pragma unroll 8
    for (int j = 0; j < HD; j++) {
        float hv = hr[j];
        s0 += hv * W1[j * HD + k0];
        s1 += hv * W1[j * HD + k0 + 1];
    }
    s0 = lrelu(s0); s1 = lrelu(s1);
    float part = s0 * W2[k0] + s1 * W2[k0 + 1];
#pragma unroll
    for (int o = 16; o; o >>= 1) part += __shfl_xor_sync(0xffffffffu, part, o);
    if (l == 0) {
        float sc = part + b2[0];
        g_score[n] = sc;
        atomicMax(&g_smax[b], f2o(sc));
    }
}

__global__ void exp_kernel(const int* __restrict__ batch, int N)
{
    int n = blockIdx.x * blockDim.x + threadIdx.x;
    if (n >= N) return;
    int b = batch[n];
    float ev = expf(g_score[n] - o2f(g_smax[b]));
    g_ex[n] = ev;
    atomicAdd(&g_denom[b], ev);
}

__global__ void pool_kernel(const int* __restrict__ batch, int N)
{
    int n = (blockIdx.x * blockDim.x + threadIdx.x) >> 5;
    if (n >= N) return;
    int l = threadIdx.x & 31;
    int b = batch[n];
    float w = g_ex[n] / g_denom[b];
    int k0 = 2 * l;
    atomicAdd(&g_pooled[b * HD + k0],     g_h[(size_t)n * HD + k0] * w);
    atomicAdd(&g_pooled[b * HD + k0 + 1], g_h[(size_t)n * HD + k0 + 1] * w);
}

__global__ void out_kernel(const float* __restrict__ W1, const float* __restrict__ b1,
                           const float* __restrict__ W2, const float* __restrict__ b2,
                           float* __restrict__ out)
{
    int g = blockIdx.x;
    int k = threadIdx.x;
    __shared__ float ps[HD];
    __shared__ float red[HD];
    ps[k] = g_pooled[g * HD + k];
    __syncthreads();
    float acc = b1[k];
#pragma unroll 8
    for (int j = 0; j < HD; j++) acc += ps[j] * W1[j * HD + k];
    acc = fmaxf(acc, 0.f);
    red[k] = acc * W2[k];
    __syncthreads();
    for (int o = 32; o; o >>= 1) {
        if (k < o) red[k] += red[k + o];
        __syncthreads();
    }
    if (k == 0) out[g] = red[0] + b2[0];
}

// ---------------- host launcher ---------------------------------------------
extern "C" void kernel_launch(void* const* d_in, const int* in_sizes, int n_in,
                              void* d_out, int out_size)
{
    const float* x      = (const float*)d_in[0];
    const int*   eidx   = (const int*)  d_in[1];
    const float* eattr  = (const float*)d_in[2];
    const int*   batch  = (const int*)  d_in[3];
    const float* gfeat  = (const float*)d_in[4];
    const float* node_W = (const float*)d_in[5];
    const float* node_b = (const float*)d_in[6];
    const float* edge_W = (const float*)d_in[7];
    const float* edge_b = (const float*)d_in[8];
    const float* conv_W = (const float*)d_in[9];
    const float* conv_att = (const float*)d_in[10];
    const float* conv_b = (const float*)d_in[11];
    const float* conv_g = (const float*)d_in[12];
    const float* conv_be = (const float*)d_in[13];
    const float* ga_W1  = (const float*)d_in[14];
    const float* ga_b1  = (const float*)d_in[15];
    const float* ga_W2  = (const float*)d_in[16];
    const float* ga_b2  = (const float*)d_in[17];
    const float* out_W1 = (const float*)d_in[18];
    const float* out_b1 = (const float*)d_in[19];
    const float* out_W2 = (const float*)d_in[20];
    const float* out_b2 = (const float*)d_in[21];

    const int N = in_sizes[3];
    const int E = in_sizes[2] / EF;
    const int G = in_sizes[4] / GD;

    const int* row = eidx;
    const int* col = eidx + E;

    float *p_h, *p_h0, *p_ea, *p_P, *p_Q, *p_hagg, *p_denom, *p_pooled;
    float *p_Wt, *p_eat, *p_ht;
    unsigned* p_smax;
    cudaGetSymbolAddress((void**)&p_h,     g_h);
    cudaGetSymbolAddress((void**)&p_h0,    g_h0);
    cudaGetSymbolAddress((void**)&p_ea,    g_ea);
    cudaGetSymbolAddress((void**)&p_P,     g_P);
    cudaGetSymbolAddress((void**)&p_Q,     g_Q);
    cudaGetSymbolAddress((void**)&p_hagg,  g_hagg);
    cudaGetSymbolAddress((void**)&p_smax,  g_smax);
    cudaGetSymbolAddress((void**)&p_denom, g_denom);
    cudaGetSymbolAddress((void**)&p_pooled,g_pooled);
    cudaGetSymbolAddress((void**)&p_Wt,    g_Wt);
    cudaGetSymbolAddress((void**)&p_eat,   g_eat);
    cudaGetSymbolAddress((void**)&p_ht,    g_ht);

    // embeddings (fp32)
    {
        dim3 grid((N + 63) / 64, HD / 64);
        gemm_tiled<<<grid, 256>>>(x, NF, node_W, HD, node_b, p_h0, HD, N, NF, 1);
    }
    {
        dim3 grid((E + 63) / 64, HD / 64);
        gemm_tiled<<<grid, 256>>>(eattr, EF, edge_W, HD, edge_b, p_ea, HD, E, EF, 1);
    }

    // prep: transpose+round+permute conv weights; round+permute edge embedding
    prep_W<<<(NL * 2 * HW * HD + 255) / 256, 256>>>(conv_W);
    round_perm<<<(E * HD + 255) / 256, 256>>>(p_ea, p_eat, E * HD);

    const int nb1 = (N + 127) / 128;
    const int nb2 = (E + 127) / 128;

    for (int i = 0; i < NL; i++) {
        const float* attL = conv_att + (size_t)i * NHEAD * 2 * HD;
        const float* bL   = conv_b + i * HD;
        const float* gmL  = conv_g + i * NHEAD;
        const float* btL  = conv_be + i * NHEAD;
        const float* Ain  = (i == 0) ? p_h0 : p_h;

        round_perm<<<(N * HD + 255) / 256, 256>>>(Ain, p_ht, N * HD);

        const float* WP = p_Wt + (size_t)(i * 2 + 0) * HW * HD;
        const float* WQ = p_Wt + (size_t)(i * 2 + 1) * HW * HD;

        dim3 gridPQ(nb1 + nb2, HW / 128);
        gemm_mma<<<gridPQ, 256>>>(p_ht, p_eat, WP, WQ, p_P, p_Q, N, E, nb1);

        cudaMemsetAsync(p_hagg, 0, (size_t)N * HD * sizeof(float));

        int blocks = (E * 32 + 255) / 256;
        edge_kernel<<<blocks, 256>>>(row, col, attL, gmL, btL, E);

        node_update<<<(N * HD + 255) / 256, 256>>>(bL, N, i == 0, i == NL - 1);
    }

    // readout
    cudaMemsetAsync(p_smax, 0, G * sizeof(unsigned));
    cudaMemsetAsync(p_denom, 0, G * sizeof(float));
    cudaMemsetAsync(p_pooled, 0, (size_t)G * HD * sizeof(float));

    gb_kernel<<<G, HD>>>(gfeat, ga_W1, ga_b1, G);
    score_kernel<<<(N * 32 + 255) / 256, 256>>>(batch, ga_W1, ga_W2, ga_b2, N);
    exp_kernel<<<(N + 255) / 256, 256>>>(batch, N);
    pool_kernel<<<(N * 32 + 255) / 256, 256>>>(batch, N);
    out_kernel<<<G, HD>>>(out_W1, out_b1, out_W2, out_b2, (float*)d_out);
}